// round 15
// baseline (speedup 1.0000x reference)
#include <cuda_runtime.h>
#include <math.h>
#include <stdint.h>
#include <stddef.h>

// Problem constants
#define SEQ   2048
#define BATCH 64
#define INF   512
#define H     512
#define NGATE 1024
#define NTOT  1536

// Recurrence config: 128 CTAs = 64 col-groups x 2 independent batch-halves
#define G      128
#define TPB    512
#define WST    516     // padded smem row stride (floats)
#define BROWS  32      // batches per CTA

// split-K partial layout
#define CSTR   40
#define P1SL   640     // 16 cols * 40
#define P2SL   336     // 8 cols * 40 + pad

// ---------------------------------------------------------------------------
// Scratch
// ---------------------------------------------------------------------------
__device__ float g_xproj[(size_t)SEQ * BATCH * NTOT];
__device__ float g_h[BATCH * H];
__device__ float g_rh[BATCH * H];
__device__ unsigned int g_flags[128];   // [half*64 + colgroup] barrier tokens

// ---------------------------------------------------------------------------
// tf32 helpers
// ---------------------------------------------------------------------------
__device__ __forceinline__ float totf(float x) {
    uint32_t u;
    asm("cvt.rna.tf32.f32 %0, %1;" : "=r"(u) : "f"(x));
    return __uint_as_float(u);
}

__device__ __forceinline__ void mma_tf32(float& d0, float& d1, float& d2, float& d3,
                                         uint32_t a0, uint32_t a1, uint32_t a2, uint32_t a3,
                                         uint32_t b0, uint32_t b1) {
    asm volatile(
        "mma.sync.aligned.m16n8k8.row.col.f32.tf32.tf32.f32 "
        "{%0,%1,%2,%3}, {%4,%5,%6,%7}, {%8,%9}, {%0,%1,%2,%3};\n"
        : "+f"(d0), "+f"(d1), "+f"(d2), "+f"(d3)
        : "r"(a0), "r"(a1), "r"(a2), "r"(a3), "r"(b0), "r"(b1));
}

// ---------------------------------------------------------------------------
// Kernel 1: tf32 tensor-core projection GEMM (unchanged from round 13)
// ---------------------------------------------------------------------------
#define KC 20

__global__ void __launch_bounds__(256, 2)
xproj_kernel(const float* __restrict__ X,
             const float* __restrict__ Wg,
             const float* __restrict__ bg,
             const float* __restrict__ Wc,
             const float* __restrict__ bc) {
    __shared__ float As[128 * KC];
    __shared__ float Bs[128 * KC];

    const int tid = threadIdx.x;
    const int n0  = blockIdx.x * 128;
    const size_t m0 = (size_t)blockIdx.y * 128;

    const bool is_gate = (n0 < NGATE);
    const float* Bbase = is_gate ? (Wg + n0) : (Wc + (n0 - NGATE));
    const int    ldB   = is_gate ? NGATE : H;
    const float* bias  = is_gate ? (bg + n0) : (bc + (n0 - NGATE));

    const int lane = tid & 31;
    const int wrp  = tid >> 5;
    const int grp  = lane >> 2;
    const int tig  = lane & 3;
    const int m0w  = (wrp & 1) * 64;
    const int n0w  = (wrp >> 1) * 32;

    const int amA[2] = { tid >> 2, (tid + 256) >> 2 };
    const int akA    = (tid & 3) * 4;
    const int bkB[2] = { tid >> 5, (tid >> 5) + 8 };
    const int bnB    = (tid & 31) * 4;

    float acc[4][4][4];
#pragma unroll
    for (int mi = 0; mi < 4; mi++)
#pragma unroll
        for (int ni = 0; ni < 4; ni++)
#pragma unroll
            for (int r = 0; r < 4; r++) acc[mi][ni][r] = 0.f;

    float4 aR[2], bR[2];
#pragma unroll
    for (int r = 0; r < 2; r++) {
        aR[r] = *(const float4*)(X + (m0 + amA[r]) * INF + akA);
        bR[r] = *(const float4*)(Bbase + (size_t)bkB[r] * ldB + bnB);
    }

#pragma unroll 1
    for (int kc = 0; kc < INF / 16; kc++) {
#pragma unroll
        for (int r = 0; r < 2; r++) {
            float* ap = As + amA[r] * KC + akA;
            ap[0] = totf(aR[r].x); ap[1] = totf(aR[r].y);
            ap[2] = totf(aR[r].z); ap[3] = totf(aR[r].w);
            Bs[(bnB + 0) * KC + bkB[r]] = totf(bR[r].x);
            Bs[(bnB + 1) * KC + bkB[r]] = totf(bR[r].y);
            Bs[(bnB + 2) * KC + bkB[r]] = totf(bR[r].z);
            Bs[(bnB + 3) * KC + bkB[r]] = totf(bR[r].w);
        }
        __syncthreads();

        if (kc + 1 < INF / 16) {
            const int k0 = (kc + 1) * 16;
#pragma unroll
            for (int r = 0; r < 2; r++) {
                aR[r] = *(const float4*)(X + (m0 + amA[r]) * INF + k0 + akA);
                bR[r] = *(const float4*)(Bbase + (size_t)(k0 + bkB[r]) * ldB + bnB);
            }
        }

#pragma unroll
        for (int kk = 0; kk < 16; kk += 8) {
            uint32_t af[4][4], bf[4][2];
#pragma unroll
            for (int mi = 0; mi < 4; mi++) {
                const float* ap = As + (m0w + mi * 16 + grp) * KC + kk + tig;
                af[mi][0] = __float_as_uint(ap[0]);
                af[mi][1] = __float_as_uint(ap[8 * KC]);
                af[mi][2] = __float_as_uint(ap[4]);
                af[mi][3] = __float_as_uint(ap[8 * KC + 4]);
            }
#pragma unroll
            for (int ni = 0; ni < 4; ni++) {
                const float* bp = Bs + (n0w + ni * 8 + grp) * KC + kk + tig;
                bf[ni][0] = __float_as_uint(bp[0]);
                bf[ni][1] = __float_as_uint(bp[4]);
            }
#pragma unroll
            for (int mi = 0; mi < 4; mi++)
#pragma unroll
                for (int ni = 0; ni < 4; ni++)
                    mma_tf32(acc[mi][ni][0], acc[mi][ni][1],
                             acc[mi][ni][2], acc[mi][ni][3],
                             af[mi][0], af[mi][1], af[mi][2], af[mi][3],
                             bf[ni][0], bf[ni][1]);
        }
        __syncthreads();
    }

#pragma unroll
    for (int ni = 0; ni < 4; ni++) {
        const int cl = n0w + ni * 8 + 2 * tig;
        const float bz0 = bias[cl];
        const float bz1 = bias[cl + 1];
#pragma unroll
        for (int mi = 0; mi < 4; mi++) {
            const size_t r0 = m0 + m0w + mi * 16 + grp;
            float2 v0 = { acc[mi][ni][0] + bz0, acc[mi][ni][1] + bz1 };
            float2 v1 = { acc[mi][ni][2] + bz0, acc[mi][ni][3] + bz1 };
            *(float2*)(g_xproj + r0 * NTOT + n0 + cl)       = v0;
            *(float2*)(g_xproj + (r0 + 8) * NTOT + n0 + cl) = v1;
        }
    }
}

// ---------------------------------------------------------------------------
// h0 -> g_h, and reset barrier flags (runs before persistent kernel each replay)
// ---------------------------------------------------------------------------
__global__ void init_h_kernel(const float* __restrict__ h0) {
    int i = blockIdx.x * blockDim.x + threadIdx.x;
    if (i < BATCH * H) g_h[i] = h0[i];
    if (i < 128) g_flags[i] = 0u;
}

// ---------------------------------------------------------------------------
// Kernel 2: persistent GRU recurrence, per-half distributed-flag barriers.
// ---------------------------------------------------------------------------
__global__ void __launch_bounds__(TPB, 1)
gru_persistent_kernel(const float* __restrict__ Wg,
                      const float* __restrict__ Wc,
                      float* __restrict__ out,
                      int write_hlast) {
    extern __shared__ float smem[];
    float* sW    = smem;                 // 24 cols * WST, tf32
    float* sh    = sW + 24 * WST;        // 32 rows * WST, tf32 (h, then rh)
    float* sPart = sh + BROWS * WST;     // 2688
    float* sZ    = sPart + 2688;         // 32 * 8
    float* sHF   = sZ + BROWS * 8;       // 32 * 8 exact fp32 h (own cols)

    const int cta = blockIdx.x;
    const int tid = threadIdx.x;
    const int c0  = (cta >> 1) * 8;
    const int b0  = (cta & 1) * BROWS;

    // barrier bookkeeping: flags grouped per half on separate 256B regions
    const int fidx  = (cta & 1) * 64 + (cta >> 1);   // my flag
    const int pbase = (cta & 1) * 64;                // my half's flag base
    unsigned int tok = 0;

#define HALF_BARRIER()                                                          \
    do {                                                                        \
        tok++;                                                                  \
        __threadfence();                                                        \
        __syncthreads();                                                        \
        if (tid == 0) *(volatile unsigned int*)&g_flags[fidx] = tok;            \
        if (tid < 64) {                                                         \
            while (*(volatile unsigned int*)&g_flags[pbase + tid] < tok) { }    \
        }                                                                       \
        __syncthreads();                                                        \
    } while (0)

    const int lane = tid & 31;
    const int wrp  = tid >> 5;
    const int grp  = lane >> 2;
    const int tig  = lane & 3;

    // resident weights (tf32-rounded): 24 columns of 512
    for (int i = tid; i < 24 * INF; i += TPB) {
        int j = i >> 9;
        int k = i & (INF - 1);
        float v;
        if (j < 8)       v = Wg[(size_t)(INF + k) * NGATE + c0 + j];
        else if (j < 16) v = Wg[(size_t)(INF + k) * NGATE + H + c0 + (j - 8)];
        else             v = Wc[(size_t)(INF + k) * H + c0 + (j - 16)];
        sW[j * WST + k] = totf(v);
    }
    __syncthreads();

    const int mt1 = wrp & 1, nt1 = (wrp >> 1) & 1, kr1 = wrp >> 2;
    const float* aB1 = sh + (mt1 * 16 + grp) * WST + kr1 * 128 + tig;
    const float* bB1 = sW + (nt1 * 8 + grp) * WST + kr1 * 128 + tig;
    const int mt2 = wrp & 1, kr2 = wrp >> 1;
    const float* aB2 = sh + (mt2 * 16 + grp) * WST + kr2 * 64 + tig;
    const float* bB2 = sW + (16 + grp) * WST + kr2 * 64 + tig;

    const int fcol = tig * 2;
    const int fbat1 = mt1 * 16 + grp;

    const int c1 = tid >> 5, b1 = tid & 31;
    const int gcol = (c1 < 8) ? (c0 + c1) : (H + c0 + (c1 - 8));
    const int c2o = tid >> 5, b2o = tid & 31;

    // preloop prefetch of step-0 gate projection (DRAM)
    float xg = __ldg(g_xproj + (size_t)(b0 + b1) * NTOT + gcol);

    for (int t = 0; t < SEQ; t++) {
        const size_t xbase = (size_t)t * BATCH * NTOT;

        // ---- stage h rows [b0, b0+32): tf32 into sh, exact fp32 own-cols ----
#pragma unroll
        for (int n = 0; n < 8; n++) {
            int i = tid + n * 512;
            int row = i >> 7;
            int cc  = (i & 127) * 4;
            float4 v = __ldcg((const float4*)(g_h + (size_t)(b0 + row) * H + cc));
            v.x = totf(v.x); v.y = totf(v.y); v.z = totf(v.z); v.w = totf(v.w);
            *(float4*)(sh + row * WST + cc) = v;
        }
        if (tid < BROWS * 8) {
            int b = tid >> 3, c = tid & 7;
            sHF[tid] = __ldcg(g_h + (size_t)(b0 + b) * H + c0 + c);
        }
        __syncthreads();

        // ---- phase 1: gate GEMM ----
        {
            float d0 = 0.f, d1 = 0.f, d2 = 0.f, d3 = 0.f;
#pragma unroll
            for (int ks = 0; ks < 16; ks++) {
                const int off = ks * 8;
                uint32_t a0 = __float_as_uint(aB1[off]);
                uint32_t a1 = __float_as_uint(aB1[8 * WST + off]);
                uint32_t a2 = __float_as_uint(aB1[off + 4]);
                uint32_t a3 = __float_as_uint(aB1[8 * WST + off + 4]);
                uint32_t b0r = __float_as_uint(bB1[off]);
                uint32_t b1r = __float_as_uint(bB1[off + 4]);
                mma_tf32(d0, d1, d2, d3, a0, a1, a2, a3, b0r, b1r);
            }
            float* pb = sPart + kr1 * P1SL;
            const int colL = nt1 * 8 + fcol;
            pb[(colL + 0) * CSTR + fbat1]     = d0;
            pb[(colL + 1) * CSTR + fbat1]     = d1;
            pb[(colL + 0) * CSTR + fbat1 + 8] = d2;
            pb[(colL + 1) * CSTR + fbat1 + 8] = d3;
        }
        __syncthreads();

        // ---- phase 1 reduction + activation ----
        {
            float s = xg;
#pragma unroll
            for (int q = 0; q < 4; q++)
                s += sPart[q * P1SL + c1 * CSTR + b1];
            float sig = 1.f / (1.f + expf(-s));
            if (c1 < 8) {
                sZ[b1 * 8 + c1] = sig;
            } else {
                int cc = c1 - 8;
                g_rh[(size_t)(b0 + b1) * H + c0 + cc] = sig * sHF[b1 * 8 + cc];
            }
        }

        // prefetch cand projection BEFORE the barrier (overlap DRAM latency)
        float xc = 0.f;
        if (tid < 256)
            xc = __ldg(g_xproj + xbase + (size_t)(b0 + b2o) * NTOT + NGATE + c0 + c2o);

        HALF_BARRIER();   // publish g_rh within my batch-half

        // ---- stage rh rows [b0, b0+32) as tf32 ----
#pragma unroll
        for (int n = 0; n < 8; n++) {
            int i = tid + n * 512;
            int row = i >> 7;
            int cc  = (i & 127) * 4;
            float4 v = __ldcg((const float4*)(g_rh + (size_t)(b0 + row) * H + cc));
            v.x = totf(v.x); v.y = totf(v.y); v.z = totf(v.z); v.w = totf(v.w);
            *(float4*)(sh + row * WST + cc) = v;
        }
        __syncthreads();

        // ---- phase 2: candidate GEMM ----
        {
            float d0 = 0.f, d1 = 0.f, d2 = 0.f, d3 = 0.f;
#pragma unroll
            for (int ks = 0; ks < 8; ks++) {
                const int off = ks * 8;
                uint32_t a0 = __float_as_uint(aB2[off]);
                uint32_t a1 = __float_as_uint(aB2[8 * WST + off]);
                uint32_t a2 = __float_as_uint(aB2[off + 4]);
                uint32_t a3 = __float_as_uint(aB2[8 * WST + off + 4]);
                uint32_t b0r = __float_as_uint(bB2[off]);
                uint32_t b1r = __float_as_uint(bB2[off + 4]);
                mma_tf32(d0, d1, d2, d3, a0, a1, a2, a3, b0r, b1r);
            }
            float* pb = sPart + kr2 * P2SL;
            const int fbat2 = mt2 * 16 + grp;
            pb[(fcol + 0) * CSTR + fbat2]     = d0;
            pb[(fcol + 1) * CSTR + fbat2]     = d1;
            pb[(fcol + 0) * CSTR + fbat2 + 8] = d2;
            pb[(fcol + 1) * CSTR + fbat2 + 8] = d3;
        }
        __syncthreads();

        // ---- phase 2 reduction + h update ----
        if (tid < 256) {
            float sum = xc;
#pragma unroll
            for (int q = 0; q < 8; q++)
                sum += sPart[q * P2SL + c2o * CSTR + b2o];
            float cand = tanhf(sum);
            float hold = sHF[b2o * 8 + c2o];
            float z    = sZ[b2o * 8 + c2o];
            float hn   = hold + z * (cand - hold);
            int gb = b0 + b2o;
            g_h[(size_t)gb * H + c0 + c2o] = hn;
            out[((size_t)t * BATCH + gb) * H + c0 + c2o] = hn;
            if (write_hlast && t == SEQ - 1)
                out[(size_t)SEQ * BATCH * H + (size_t)gb * H + c0 + c2o] = hn;
        }

        // prefetch next step's gate projection BEFORE the barrier
        if (t + 1 < SEQ)
            xg = __ldg(g_xproj + (xbase + (size_t)BATCH * NTOT) +
                       (size_t)(b0 + b1) * NTOT + gcol);

        HALF_BARRIER();   // publish g_h within my batch-half
    }
#undef HALF_BARRIER
}

// ---------------------------------------------------------------------------
// Launch
// ---------------------------------------------------------------------------
extern "C" void kernel_launch(void* const* d_in, const int* in_sizes, int n_in,
                              void* d_out, int out_size) {
    const float* x  = (const float*)d_in[0];
    const float* h0 = (const float*)d_in[1];
    const float* Wg = (const float*)d_in[2];
    const float* bg = (const float*)d_in[3];
    const float* Wc = (const float*)d_in[4];
    const float* bc = (const float*)d_in[5];
    float* out = (float*)d_out;

    (void)in_sizes; (void)n_in;

    dim3 g1(NTOT / 128, (SEQ * BATCH) / 128);
    xproj_kernel<<<g1, 256>>>(x, Wg, bg, Wc, bc);

    init_h_kernel<<<(BATCH * H + 255) / 256, 256>>>(h0);

    const int smem_bytes =
        (24 * WST + BROWS * WST + 2688 + BROWS * 8 * 2) * (int)sizeof(float);
    cudaFuncSetAttribute(gru_persistent_kernel,
                         cudaFuncAttributeMaxDynamicSharedMemorySize, smem_bytes);
    int write_hlast = (out_size >= SEQ * BATCH * H + BATCH * H) ? 1 : 0;
    gru_persistent_kernel<<<G, TPB, smem_bytes>>>(Wg, Wc, out, write_hlast);
}